// round 9
// baseline (speedup 1.0000x reference)
#include <cuda_runtime.h>
#include <math.h>
#include <stdint.h>

// Problem constants (fixed shapes from reference)
#define BB 4
#define LL 2048
#define DD 768
#define SS 16
#define MM (BB * LL)          // 8192
#define TWO_D (2 * DD)        // 1536
#define NC 16                 // scan chunks
#define LC (LL / NC)          // 128

// ---------------- scratch (device globals; no allocs allowed) ----------------
__device__ float g_xz[MM * TWO_D];     // in_proj output (x_gate | z)
__device__ float g_xconv[MM * DD];     // conv + silu output
__device__ float g_dt[MM * DD];        // softplus(dt)
__device__ float g_bc[MM * 2 * SS];    // B | C
__device__ float g_yg[MM * DD];        // scan output * silu(z)
__device__ float g_P[BB * DD * NC * SS];     // per-chunk decay products
__device__ float g_hend[BB * DD * NC * SS];  // per-chunk local end state
__device__ float g_hin[BB * DD * NC * SS];   // per-chunk incoming state

// ---------------- mma/ldmatrix helpers ----------------
__device__ __forceinline__ void ldsm_x4(uint32_t& r0, uint32_t& r1,
                                        uint32_t& r2, uint32_t& r3, uint32_t addr)
{
    asm volatile("ldmatrix.sync.aligned.m8n8.x4.shared.b16 {%0,%1,%2,%3}, [%4];"
                 : "=r"(r0), "=r"(r1), "=r"(r2), "=r"(r3) : "r"(addr));
}

__device__ __forceinline__ void ldsm_x4t(uint32_t& r0, uint32_t& r1,
                                         uint32_t& r2, uint32_t& r3, uint32_t addr)
{
    asm volatile("ldmatrix.sync.aligned.m8n8.x4.trans.shared.b16 {%0,%1,%2,%3}, [%4];"
                 : "=r"(r0), "=r"(r1), "=r"(r2), "=r"(r3) : "r"(addr));
}

__device__ __forceinline__ void mma16816(float* c, const uint32_t* a, const uint32_t* b)
{
    asm volatile(
        "mma.sync.aligned.m16n8k16.row.col.f32.bf16.bf16.f32 "
        "{%0,%1,%2,%3}, {%4,%5,%6,%7}, {%8,%9}, {%0,%1,%2,%3};"
        : "+f"(c[0]), "+f"(c[1]), "+f"(c[2]), "+f"(c[3])
        : "r"(a[0]), "r"(a[1]), "r"(a[2]), "r"(a[3]), "r"(b[0]), "r"(b[1]));
}

// split two f32 into packed bf16x2 hi + bf16x2 lo (element0 in low 16 bits)
__device__ __forceinline__ void split2(float x0, float x1, uint32_t& hi, uint32_t& lo)
{
    uint32_t h;
    asm("cvt.rn.bf16x2.f32 %0, %1, %2;" : "=r"(h) : "f"(x1), "f"(x0));
    float h0 = __uint_as_float(h << 16);
    float h1 = __uint_as_float(h & 0xffff0000u);
    float l0 = x0 - h0;
    float l1 = x1 - h1;
    asm("cvt.rn.bf16x2.f32 %0, %1, %2;" : "=r"(lo) : "f"(l1), "f"(l0));
    hi = h;
}

// ---------------- 128x128 tensor-core GEMM, bf16 2-term split (3 MMAs) -------
// Double-buffered smem, KT=16, one __syncthreads per k-tile.
// C[M,N] = A[M,K] @ B[K,N] (row-major), fp32 acc, rel err ~2^-16.
// EPI: 0 = plain store, 1 = softplus(acc + bias[n])
#define A_STRIDE 12            // uint32 per A row (data 8, pad to 48B: conflict-free)
#define B_STRIDE 68            // uint32 per B row (data 64, pad to 272B: conflict-free)
#define A_BUF_BYTES (128 * A_STRIDE * 4)
#define B_BUF_BYTES (16 * B_STRIDE * 4)

template <int EPI>
__device__ __forceinline__ void gemm_mma_body(
    const float* __restrict__ A, const float* __restrict__ Bm,
    float* __restrict__ C, const float* __restrict__ bias,
    int N, int K)
{
    __shared__ uint32_t AsH[2][128][A_STRIDE];   // 12.3 KB
    __shared__ uint32_t AsL[2][128][A_STRIDE];   // 12.3 KB
    __shared__ uint32_t BsH[2][16][B_STRIDE];    // 8.7 KB
    __shared__ uint32_t BsL[2][16][B_STRIDE];    // 8.7 KB  -> total ~42 KB

    const int tid  = threadIdx.x;
    const int lane = tid & 31;
    const int wid  = tid >> 5;
    const int m_off = (wid >> 2) * 64;
    const int n_off = (wid & 3) * 32;
    const int bx = blockIdx.x, by = blockIdx.y;

    float acc[4][4][4];
#pragma unroll
    for (int i = 0; i < 4; i++)
#pragma unroll
        for (int j = 0; j < 4; j++)
#pragma unroll
            for (int r = 0; r < 4; r++) acc[i][j][r] = 0.f;

    const uint32_t aBaseH = (uint32_t)__cvta_generic_to_shared(&AsH[0][0][0]);
    const uint32_t aBaseL = (uint32_t)__cvta_generic_to_shared(&AsL[0][0][0]);
    const uint32_t bBaseH = (uint32_t)__cvta_generic_to_shared(&BsH[0][0][0]);
    const uint32_t bBaseL = (uint32_t)__cvta_generic_to_shared(&BsL[0][0][0]);

    const uint32_t aFragOff = (uint32_t)((m_off + (lane & 15)) * (A_STRIDE * 4) + 16 * (lane >> 4));
    const uint32_t bFragOff = (uint32_t)(((lane & 7) + 8 * ((lane >> 3) & 1)) * (B_STRIDE * 4)
                                         + (n_off + 8 * (lane >> 4)) * 2);

    float4 av[2], bv[2];

    auto load_tile = [&](int kt) {
#pragma unroll
        for (int i = 0; i < 2; i++) {
            int idx = tid + i * 256;
            av[i] = *(const float4*)&A[(size_t)(by * 128 + (idx >> 2)) * K + kt + (idx & 3) * 4];
            bv[i] = *(const float4*)&Bm[(size_t)(kt + (idx >> 5)) * N + bx * 128 + (idx & 31) * 4];
        }
    };
    auto store_tile = [&](int buf) {
#pragma unroll
        for (int i = 0; i < 2; i++) {
            int idx = tid + i * 256;
            {
                int row = idx >> 2, c2 = (idx & 3) * 2;
                uint32_t h0, l0, h1, l1;
                split2(av[i].x, av[i].y, h0, l0);
                split2(av[i].z, av[i].w, h1, l1);
                AsH[buf][row][c2] = h0; AsH[buf][row][c2 + 1] = h1;
                AsL[buf][row][c2] = l0; AsL[buf][row][c2 + 1] = l1;
            }
            {
                int r = idx >> 5, c2 = (idx & 31) * 2;
                uint32_t h0, l0, h1, l1;
                split2(bv[i].x, bv[i].y, h0, l0);
                split2(bv[i].z, bv[i].w, h1, l1);
                BsH[buf][r][c2] = h0; BsH[buf][r][c2 + 1] = h1;
                BsL[buf][r][c2] = l0; BsL[buf][r][c2 + 1] = l1;
            }
        }
    };

    load_tile(0);
    store_tile(0);
    __syncthreads();

    int p = 0;
    for (int kt = 0; kt < K; kt += 16) {
        const bool more = (kt + 16) < K;
        if (more) load_tile(kt + 16);

        // fragments from buffer p
        const uint32_t aOff = (uint32_t)(p * A_BUF_BYTES);
        const uint32_t bOff = (uint32_t)(p * B_BUF_BYTES);
        uint32_t ah[4][4], al[4][4], bh[4][2], bl[4][2];
#pragma unroll
        for (int i = 0; i < 4; i++) {
            uint32_t off = aFragOff + (uint32_t)(i * 16 * (A_STRIDE * 4)) + aOff;
            ldsm_x4(ah[i][0], ah[i][1], ah[i][2], ah[i][3], aBaseH + off);
            ldsm_x4(al[i][0], al[i][1], al[i][2], al[i][3], aBaseL + off);
        }
#pragma unroll
        for (int jj = 0; jj < 2; jj++) {
            uint32_t off = bFragOff + (uint32_t)(jj * 32) + bOff;
            uint32_t r0, r1, r2, r3;
            ldsm_x4t(r0, r1, r2, r3, bBaseH + off);
            bh[2 * jj][0] = r0; bh[2 * jj][1] = r1;
            bh[2 * jj + 1][0] = r2; bh[2 * jj + 1][1] = r3;
            ldsm_x4t(r0, r1, r2, r3, bBaseL + off);
            bl[2 * jj][0] = r0; bl[2 * jj][1] = r1;
            bl[2 * jj + 1][0] = r2; bl[2 * jj + 1][1] = r3;
        }

        // overlap: convert+store next tile into the other buffer while
        // ldmatrix results are in flight (readers of buf p^1 finished last bar)
        if (more) store_tile(p ^ 1);

#pragma unroll
        for (int i = 0; i < 4; i++)
#pragma unroll
            for (int j = 0; j < 4; j++) {
                mma16816(acc[i][j], ah[i], bh[j]);
                mma16816(acc[i][j], ah[i], bl[j]);
                mma16816(acc[i][j], al[i], bh[j]);
            }

        __syncthreads();
        p ^= 1;
    }

#pragma unroll
    for (int i = 0; i < 4; i++) {
        int row0 = by * 128 + m_off + 16 * i + (lane >> 2);
#pragma unroll
        for (int j = 0; j < 4; j++) {
            int col0 = bx * 128 + n_off + 8 * j + 2 * (lane & 3);
            float v0 = acc[i][j][0], v1 = acc[i][j][1];
            float v2 = acc[i][j][2], v3 = acc[i][j][3];
            if (EPI == 1) {
                float b0 = bias[col0], b1 = bias[col0 + 1], t;
                t = v0 + b0; v0 = (t > 20.f) ? t : log1pf(expf(t));
                t = v1 + b1; v1 = (t > 20.f) ? t : log1pf(expf(t));
                t = v2 + b0; v2 = (t > 20.f) ? t : log1pf(expf(t));
                t = v3 + b1; v3 = (t > 20.f) ? t : log1pf(expf(t));
            }
            *(float2*)&C[(size_t)row0 * N + col0] = make_float2(v0, v1);
            *(float2*)&C[(size_t)(row0 + 8) * N + col0] = make_float2(v2, v3);
        }
    }
}

__global__ __launch_bounds__(256) void gemm_in_kernel(
    const float* __restrict__ x, const float* __restrict__ w_in)
{
    gemm_mma_body<0>(x, w_in, g_xz, nullptr, TWO_D, DD);
}

__global__ __launch_bounds__(256) void gemm_dt_kernel(
    const float* __restrict__ w_dt, const float* __restrict__ b_dt)
{
    gemm_mma_body<1>(g_xconv, w_dt, g_dt, b_dt, DD, DD);
}

__global__ __launch_bounds__(256) void gemm_out_kernel(
    const float* __restrict__ w_out, float* __restrict__ out)
{
    gemm_mma_body<0>(g_yg, w_out, out, nullptr, DD, DD);
}

// ---------------- causal depthwise conv (K=4) + bias + SiLU ----------------
__global__ void conv_silu_kernel(const float* __restrict__ cw,
                                 const float* __restrict__ cb)
{
    int idx = blockIdx.x * blockDim.x + threadIdx.x;
    if (idx >= MM * DD) return;
    int d  = idx % DD;
    int ml = idx / DD;
    int l  = ml % LL;

    float w0 = cw[d * 4 + 0], w1 = cw[d * 4 + 1];
    float w2 = cw[d * 4 + 2], w3 = cw[d * 4 + 3];
    const float* base = g_xz + (size_t)ml * TWO_D + d;

    float acc = cb[d];
    if (l >= 3) acc = fmaf(w0, base[-3 * TWO_D], acc);
    if (l >= 2) acc = fmaf(w1, base[-2 * TWO_D], acc);
    if (l >= 1) acc = fmaf(w2, base[-1 * TWO_D], acc);
    acc = fmaf(w3, base[0], acc);

    float sig = 1.f / (1.f + expf(-acc));
    g_xconv[idx] = acc * sig;
}

// ---------------- BC = xconv @ w_x   (M=8192, N=32, K=768) ----------------
// Split-K by 2: 256 threads = 128 rows x 2 k-halves; smem reduce at end.
__global__ __launch_bounds__(256) void bc_gemm_kernel(const float* __restrict__ wx)
{
    __shared__ float ws[64][32];     // 8 KB
    __shared__ float xs[128][65];    // 33.3 KB (aliased as reduce buffer later)

    const int tid  = threadIdx.x;
    const int row  = tid & 127;
    const int half = tid >> 7;
    const int row0 = blockIdx.x * 128;

    float acc[32];
#pragma unroll
    for (int n = 0; n < 32; n++) acc[n] = 0.f;

    for (int k0 = 0; k0 < DD; k0 += 64) {
#pragma unroll
        for (int i = 0; i < 2; i++) {
            int idx = tid + i * 256;
            int r = idx >> 3;
            int c4 = (idx & 7) * 4;
            *(float4*)&ws[r][c4] = *(const float4*)&wx[(size_t)(k0 + r) * 32 + c4];
        }
#pragma unroll
        for (int i = 0; i < 8; i++) {
            int idx = tid + i * 256;
            int r = idx >> 4;
            int c4 = (idx & 15) * 4;
            float4 v = *(const float4*)&g_xconv[(size_t)(row0 + r) * DD + k0 + c4];
            xs[r][c4 + 0] = v.x;
            xs[r][c4 + 1] = v.y;
            xs[r][c4 + 2] = v.z;
            xs[r][c4 + 3] = v.w;
        }
        __syncthreads();
#pragma unroll 4
        for (int k = 0; k < 32; k++) {
            int kk = half * 32 + k;
            float xv = xs[row][kk];
#pragma unroll
            for (int n = 0; n < 32; n++)
                acc[n] = fmaf(xv, ws[kk][n], acc[n]);
        }
        __syncthreads();
    }

    float* red = &xs[0][0];
    if (half == 1) {
#pragma unroll
        for (int n = 0; n < 32; n++) red[row * 33 + n] = acc[n];
    }
    __syncthreads();
    if (half == 0) {
#pragma unroll
        for (int n = 0; n < 32; n++) acc[n] += red[row * 33 + n];
        float* op = g_bc + (size_t)(row0 + row) * 32;
#pragma unroll
        for (int n4 = 0; n4 < 8; n4++) {
            float4 v;
            v.x = acc[n4 * 4 + 0];
            v.y = acc[n4 * 4 + 1];
            v.z = acc[n4 * 4 + 2];
            v.w = acc[n4 * 4 + 3];
            *(float4*)(op + n4 * 4) = v;
        }
    }
}

// ---------------- chunked selective scan (3 phases) ----------------
__global__ __launch_bounds__(256) void scan_phase1(const float* __restrict__ A_log)
{
    const int tid = threadIdx.x;
    const int s = tid & 15;
    const int G = blockIdx.x * 16 + (tid >> 4);   // (b*NC + c)*DD + d
    const int d = G % DD;
    const int t2 = G / DD;
    const int c = t2 % NC;
    const int b = t2 / NC;

    const float Acoef = -expf(A_log[d * SS + s]);
    const int l0 = c * LC;
    const float* dtp = g_dt    + ((size_t)(b * LL + l0)) * DD + d;
    const float* xcp = g_xconv + ((size_t)(b * LL + l0)) * DD + d;
    const float* bcp = g_bc    + ((size_t)(b * LL + l0)) * 32;

    float h = 0.f, P = 1.f;
    for (int i = 0; i < LC; i++) {
        float dtv = dtp[(size_t)i * DD];
        float xcv = xcp[(size_t)i * DD];
        float Bv  = bcp[i * 32 + s];
        float dA = expf(dtv * Acoef);
        P *= dA;
        h = fmaf(dA, h, dtv * Bv * xcv);
    }
    int idx = (((b * DD + d) * NC) + c) * SS + s;
    g_P[idx] = P;
    g_hend[idx] = h;
}

__global__ __launch_bounds__(256) void scan_phase2()
{
    int t = blockIdx.x * 256 + threadIdx.x;    // < BB*DD*SS
    int s = t & 15;
    int rest = t >> 4;                          // b*DD + d
    int base = rest * NC * SS + s;
    float h = 0.f;
#pragma unroll
    for (int c = 0; c < NC; c++) {
        int idx = base + c * SS;
        g_hin[idx] = h;
        h = fmaf(g_P[idx], h, g_hend[idx]);
    }
}

__global__ __launch_bounds__(256) void scan_phase3(
    const float* __restrict__ A_log, const float* __restrict__ Dp)
{
    const int tid = threadIdx.x;
    const int s = tid & 15;
    const int G = blockIdx.x * 16 + (tid >> 4);
    const int d = G % DD;
    const int t2 = G / DD;
    const int c = t2 % NC;
    const int b = t2 / NC;

    const float Acoef = -expf(A_log[d * SS + s]);
    const float Dv = Dp[d];
    const int l0 = c * LC;

    const float* dtp = g_dt    + ((size_t)(b * LL + l0)) * DD + d;
    const float* xcp = g_xconv + ((size_t)(b * LL + l0)) * DD + d;
    const float* bcp = g_bc    + ((size_t)(b * LL + l0)) * 32;
    const float* zp  = g_xz    + ((size_t)(b * LL + l0)) * TWO_D + DD + d;
    float*       yp  = g_yg    + ((size_t)(b * LL + l0)) * DD + d;

    float h = g_hin[(((b * DD + d) * NC) + c) * SS + s];
    for (int i = 0; i < LC; i++) {
        float dtv = dtp[(size_t)i * DD];
        float xcv = xcp[(size_t)i * DD];
        float Bv  = bcp[i * 32 + s];
        float Cv  = bcp[i * 32 + 16 + s];

        float dA = expf(dtv * Acoef);
        h = fmaf(dA, h, dtv * Bv * xcv);

        float p = h * Cv;
        p += __shfl_xor_sync(0xffffffffu, p, 8);
        p += __shfl_xor_sync(0xffffffffu, p, 4);
        p += __shfl_xor_sync(0xffffffffu, p, 2);
        p += __shfl_xor_sync(0xffffffffu, p, 1);

        if (s == 0) {
            float y = fmaf(Dv, xcv, p);
            float zv = zp[(size_t)i * TWO_D];
            float gz = zv / (1.f + expf(-zv));
            yp[(size_t)i * DD] = y * gz;
        }
    }
}

// ---------------- launch ----------------
extern "C" void kernel_launch(void* const* d_in, const int* in_sizes, int n_in,
                              void* d_out, int out_size)
{
    const float* x      = (const float*)d_in[0];
    const float* w_in   = (const float*)d_in[1];
    const float* conv_w = (const float*)d_in[2];
    const float* conv_b = (const float*)d_in[3];
    const float* w_x    = (const float*)d_in[4];
    const float* w_dt   = (const float*)d_in[5];
    const float* b_dt   = (const float*)d_in[6];
    const float* A_log  = (const float*)d_in[7];
    const float* D_par  = (const float*)d_in[8];
    const float* w_out  = (const float*)d_in[9];
    float* out = (float*)d_out;

    // 0. xz = x @ w_in                       (8192 x 1536, K=768)
    gemm_in_kernel<<<dim3(TWO_D / 128, MM / 128), 256>>>(x, w_in);

    // 1. causal depthwise conv + SiLU
    conv_silu_kernel<<<(MM * DD + 255) / 256, 256>>>(conv_w, conv_b);

    // 2. BC = xconv @ w_x                    (8192 x 32, K=768)
    bc_gemm_kernel<<<MM / 128, 256>>>(w_x);

    // 3. dt = softplus(xconv @ w_dt + b_dt)  (8192 x 768, K=768)  [profile slot]
    gemm_dt_kernel<<<dim3(DD / 128, MM / 128), 256>>>(w_dt, b_dt);

    // 4-6. chunked selective scan + gating   -> yg
    scan_phase1<<<(BB * DD * NC) / 16, 256>>>(A_log);
    scan_phase2<<<(BB * DD * SS) / 256, 256>>>();
    scan_phase3<<<(BB * DD * NC) / 16, 256>>>(A_log, D_par);

    // 7. out = yg @ w_out                    (8192 x 768, K=768)
    gemm_out_kernel<<<dim3(DD / 128, MM / 128), 256>>>(w_out, out);
}

// round 12
// speedup vs baseline: 1.0529x; 1.0529x over previous
#include <cuda_runtime.h>
#include <math.h>
#include <stdint.h>

// Problem constants (fixed shapes from reference)
#define BB 4
#define LL 2048
#define DD 768
#define SS 16
#define MM (BB * LL)          // 8192
#define TWO_D (2 * DD)        // 1536
#define KT 32                 // GEMM k-tile
#define NC 16                 // scan chunks
#define LC (LL / NC)          // 128

// ---------------- scratch (device globals; no allocs allowed) ----------------
__device__ float g_xz[MM * TWO_D];     // in_proj output (x_gate | z)
__device__ float g_xconv[MM * DD];     // conv + silu output
__device__ float g_dt[MM * DD];        // softplus(dt)
__device__ float g_bc[MM * 2 * SS];    // B | C
__device__ float g_yg[MM * DD];        // scan output * silu(z)
__device__ float g_P[BB * DD * NC * SS];     // per-chunk decay products
__device__ float g_hend[BB * DD * NC * SS];  // per-chunk local end state
__device__ float g_hin[BB * DD * NC * SS];   // per-chunk incoming state

// ---------------- mma/ldmatrix helpers ----------------
__device__ __forceinline__ void ldsm_x4(uint32_t& r0, uint32_t& r1,
                                        uint32_t& r2, uint32_t& r3, uint32_t addr)
{
    asm volatile("ldmatrix.sync.aligned.m8n8.x4.shared.b16 {%0,%1,%2,%3}, [%4];"
                 : "=r"(r0), "=r"(r1), "=r"(r2), "=r"(r3) : "r"(addr));
}

__device__ __forceinline__ void ldsm_x4t(uint32_t& r0, uint32_t& r1,
                                         uint32_t& r2, uint32_t& r3, uint32_t addr)
{
    asm volatile("ldmatrix.sync.aligned.m8n8.x4.trans.shared.b16 {%0,%1,%2,%3}, [%4];"
                 : "=r"(r0), "=r"(r1), "=r"(r2), "=r"(r3) : "r"(addr));
}

__device__ __forceinline__ void mma16816(float* c, const uint32_t* a, const uint32_t* b)
{
    asm volatile(
        "mma.sync.aligned.m16n8k16.row.col.f32.bf16.bf16.f32 "
        "{%0,%1,%2,%3}, {%4,%5,%6,%7}, {%8,%9}, {%0,%1,%2,%3};"
        : "+f"(c[0]), "+f"(c[1]), "+f"(c[2]), "+f"(c[3])
        : "r"(a[0]), "r"(a[1]), "r"(a[2]), "r"(a[3]), "r"(b[0]), "r"(b[1]));
}

// split two f32 into packed bf16x2 hi + bf16x2 lo (element0 in low 16 bits)
__device__ __forceinline__ void split2(float x0, float x1, uint32_t& hi, uint32_t& lo)
{
    uint32_t h;
    asm("cvt.rn.bf16x2.f32 %0, %1, %2;" : "=r"(h) : "f"(x1), "f"(x0));
    float h0 = __uint_as_float(h << 16);
    float h1 = __uint_as_float(h & 0xffff0000u);
    float l0 = x0 - h0;
    float l1 = x1 - h1;
    asm("cvt.rn.bf16x2.f32 %0, %1, %2;" : "=r"(lo) : "f"(l1), "f"(l0));
    hi = h;
}

// ---------------- 128x128 tensor-core GEMM, bf16 2-term split (3 MMAs) -------
// Single-buffer KT=32 (R7 structure), but global prefetch issued AFTER the MMA
// block so av/bv and fragment registers never co-live -> fits 128 regs ->
// __launch_bounds__(256,2) gives 2 CTAs/SM (barrier drains covered by peer CTA).
// C[M,N] = A[M,K] @ B[K,N] (row-major), fp32 acc, rel err ~2^-16.
// EPI: 0 = plain store, 1 = softplus(acc + bias[n])
template <int EPI>
__device__ __forceinline__ void gemm_mma_body(
    const float* __restrict__ A, const float* __restrict__ Bm,
    float* __restrict__ C, const float* __restrict__ bias,
    int N, int K)
{
    __shared__ uint32_t AsH[128][20];   // 128 x 32 bf16, row stride 80B
    __shared__ uint32_t AsL[128][20];
    __shared__ uint32_t BsH[32][68];    // 32 x 128 bf16, row stride 272B
    __shared__ uint32_t BsL[32][68];

    const int tid  = threadIdx.x;
    const int lane = tid & 31;
    const int wid  = tid >> 5;
    const int m_off = (wid >> 2) * 64;
    const int n_off = (wid & 3) * 32;
    const int bx = blockIdx.x, by = blockIdx.y;

    float acc[4][4][4];
#pragma unroll
    for (int i = 0; i < 4; i++)
#pragma unroll
        for (int j = 0; j < 4; j++)
#pragma unroll
            for (int r = 0; r < 4; r++) acc[i][j][r] = 0.f;

    const uint32_t aBaseH = (uint32_t)__cvta_generic_to_shared(&AsH[0][0]);
    const uint32_t aBaseL = (uint32_t)__cvta_generic_to_shared(&AsL[0][0]);
    const uint32_t bBaseH = (uint32_t)__cvta_generic_to_shared(&BsH[0][0]);
    const uint32_t bBaseL = (uint32_t)__cvta_generic_to_shared(&BsL[0][0]);

    const uint32_t aFragOff = (uint32_t)((m_off + (lane & 15)) * 80 + 16 * (lane >> 4));
    const uint32_t bFragOff = (uint32_t)(((lane & 7) + 8 * ((lane >> 3) & 1)) * 272
                                         + (n_off + 8 * (lane >> 4)) * 2);

    float4 av[4], bv[4];

    auto load_tile = [&](int kt) {
#pragma unroll
        for (int i = 0; i < 4; i++) {
            int idx = tid + i * 256;
            av[i] = *(const float4*)&A[(size_t)(by * 128 + (idx >> 3)) * K + kt + (idx & 7) * 4];
            bv[i] = *(const float4*)&Bm[(size_t)(kt + (idx >> 5)) * N + bx * 128 + (idx & 31) * 4];
        }
    };
    auto store_tile = [&]() {
#pragma unroll
        for (int i = 0; i < 4; i++) {
            int idx = tid + i * 256;
            {
                int row = idx >> 3, c2 = (idx & 7) * 2;
                uint32_t h0, l0, h1, l1;
                split2(av[i].x, av[i].y, h0, l0);
                split2(av[i].z, av[i].w, h1, l1);
                AsH[row][c2] = h0; AsH[row][c2 + 1] = h1;
                AsL[row][c2] = l0; AsL[row][c2 + 1] = l1;
            }
            {
                int r = idx >> 5, c2 = (idx & 31) * 2;
                uint32_t h0, l0, h1, l1;
                split2(bv[i].x, bv[i].y, h0, l0);
                split2(bv[i].z, bv[i].w, h1, l1);
                BsH[r][c2] = h0; BsH[r][c2 + 1] = h1;
                BsL[r][c2] = l0; BsL[r][c2 + 1] = l1;
            }
        }
    };

    load_tile(0);
    store_tile();
    __syncthreads();

    for (int kt = 0; kt < K; kt += KT) {
        const bool more = (kt + KT) < K;

#pragma unroll
        for (int ks = 0; ks < 2; ks++) {
            uint32_t ah[4][4], al[4][4], bh[4][2], bl[4][2];
#pragma unroll
            for (int i = 0; i < 4; i++) {
                uint32_t off = aFragOff + (uint32_t)(i * 16 * 80 + ks * 32);
                ldsm_x4(ah[i][0], ah[i][1], ah[i][2], ah[i][3], aBaseH + off);
                ldsm_x4(al[i][0], al[i][1], al[i][2], al[i][3], aBaseL + off);
            }
#pragma unroll
            for (int jj = 0; jj < 2; jj++) {
                uint32_t off = bFragOff + (uint32_t)(jj * 32 + ks * 16 * 272);
                uint32_t r0, r1, r2, r3;
                ldsm_x4t(r0, r1, r2, r3, bBaseH + off);
                bh[2 * jj][0] = r0; bh[2 * jj][1] = r1;
                bh[2 * jj + 1][0] = r2; bh[2 * jj + 1][1] = r3;
                ldsm_x4t(r0, r1, r2, r3, bBaseL + off);
                bl[2 * jj][0] = r0; bl[2 * jj][1] = r1;
                bl[2 * jj + 1][0] = r2; bl[2 * jj + 1][1] = r3;
            }
#pragma unroll
            for (int i = 0; i < 4; i++)
#pragma unroll
                for (int j = 0; j < 4; j++) {
                    mma16816(acc[i][j], ah[i], bh[j]);
                    mma16816(acc[i][j], ah[i], bl[j]);
                    mma16816(acc[i][j], al[i], bh[j]);
                }
        }

        // prefetch AFTER mma block: frag regs are dead here, so av/bv reuse
        // their register space (keeps us under 128 regs for 2 CTAs/SM)
        if (more) load_tile(kt + KT);
        __syncthreads();
        if (more) {
            store_tile();
            __syncthreads();
        }
    }

#pragma unroll
    for (int i = 0; i < 4; i++) {
        int row0 = by * 128 + m_off + 16 * i + (lane >> 2);
#pragma unroll
        for (int j = 0; j < 4; j++) {
            int col0 = bx * 128 + n_off + 8 * j + 2 * (lane & 3);
            float v0 = acc[i][j][0], v1 = acc[i][j][1];
            float v2 = acc[i][j][2], v3 = acc[i][j][3];
            if (EPI == 1) {
                float b0 = bias[col0], b1 = bias[col0 + 1], t;
                t = v0 + b0; v0 = (t > 20.f) ? t : log1pf(expf(t));
                t = v1 + b1; v1 = (t > 20.f) ? t : log1pf(expf(t));
                t = v2 + b0; v2 = (t > 20.f) ? t : log1pf(expf(t));
                t = v3 + b1; v3 = (t > 20.f) ? t : log1pf(expf(t));
            }
            *(float2*)&C[(size_t)row0 * N + col0] = make_float2(v0, v1);
            *(float2*)&C[(size_t)(row0 + 8) * N + col0] = make_float2(v2, v3);
        }
    }
}

__global__ __launch_bounds__(256, 2) void gemm_in_kernel(
    const float* __restrict__ x, const float* __restrict__ w_in)
{
    gemm_mma_body<0>(x, w_in, g_xz, nullptr, TWO_D, DD);
}

__global__ __launch_bounds__(256, 2) void gemm_dt_kernel(
    const float* __restrict__ w_dt, const float* __restrict__ b_dt)
{
    gemm_mma_body<1>(g_xconv, w_dt, g_dt, b_dt, DD, DD);
}

__global__ __launch_bounds__(256, 2) void gemm_out_kernel(
    const float* __restrict__ w_out, float* __restrict__ out)
{
    gemm_mma_body<0>(g_yg, w_out, out, nullptr, DD, DD);
}

// ---------------- causal depthwise conv (K=4) + bias + SiLU ----------------
__global__ void conv_silu_kernel(const float* __restrict__ cw,
                                 const float* __restrict__ cb)
{
    int idx = blockIdx.x * blockDim.x + threadIdx.x;
    if (idx >= MM * DD) return;
    int d  = idx % DD;
    int ml = idx / DD;
    int l  = ml % LL;

    float w0 = cw[d * 4 + 0], w1 = cw[d * 4 + 1];
    float w2 = cw[d * 4 + 2], w3 = cw[d * 4 + 3];
    const float* base = g_xz + (size_t)ml * TWO_D + d;

    float acc = cb[d];
    if (l >= 3) acc = fmaf(w0, base[-3 * TWO_D], acc);
    if (l >= 2) acc = fmaf(w1, base[-2 * TWO_D], acc);
    if (l >= 1) acc = fmaf(w2, base[-1 * TWO_D], acc);
    acc = fmaf(w3, base[0], acc);

    float sig = 1.f / (1.f + expf(-acc));
    g_xconv[idx] = acc * sig;
}

// ---------------- BC = xconv @ w_x   (M=8192, N=32, K=768) ----------------
// Split-K by 2: 256 threads = 128 rows x 2 k-halves; smem reduce at end.
__global__ __launch_bounds__(256) void bc_gemm_kernel(const float* __restrict__ wx)
{
    __shared__ float ws[64][32];     // 8 KB
    __shared__ float xs[128][65];    // 33.3 KB (aliased as reduce buffer later)

    const int tid  = threadIdx.x;
    const int row  = tid & 127;
    const int half = tid >> 7;
    const int row0 = blockIdx.x * 128;

    float acc[32];
#pragma unroll
    for (int n = 0; n < 32; n++) acc[n] = 0.f;

    for (int k0 = 0; k0 < DD; k0 += 64) {
#pragma unroll
        for (int i = 0; i < 2; i++) {
            int idx = tid + i * 256;
            int r = idx >> 3;
            int c4 = (idx & 7) * 4;
            *(float4*)&ws[r][c4] = *(const float4*)&wx[(size_t)(k0 + r) * 32 + c4];
        }
#pragma unroll
        for (int i = 0; i < 8; i++) {
            int idx = tid + i * 256;
            int r = idx >> 4;
            int c4 = (idx & 15) * 4;
            float4 v = *(const float4*)&g_xconv[(size_t)(row0 + r) * DD + k0 + c4];
            xs[r][c4 + 0] = v.x;
            xs[r][c4 + 1] = v.y;
            xs[r][c4 + 2] = v.z;
            xs[r][c4 + 3] = v.w;
        }
        __syncthreads();
#pragma unroll 4
        for (int k = 0; k < 32; k++) {
            int kk = half * 32 + k;
            float xv = xs[row][kk];
#pragma unroll
            for (int n = 0; n < 32; n++)
                acc[n] = fmaf(xv, ws[kk][n], acc[n]);
        }
        __syncthreads();
    }

    float* red = &xs[0][0];
    if (half == 1) {
#pragma unroll
        for (int n = 0; n < 32; n++) red[row * 33 + n] = acc[n];
    }
    __syncthreads();
    if (half == 0) {
#pragma unroll
        for (int n = 0; n < 32; n++) acc[n] += red[row * 33 + n];
        float* op = g_bc + (size_t)(row0 + row) * 32;
#pragma unroll
        for (int n4 = 0; n4 < 8; n4++) {
            float4 v;
            v.x = acc[n4 * 4 + 0];
            v.y = acc[n4 * 4 + 1];
            v.z = acc[n4 * 4 + 2];
            v.w = acc[n4 * 4 + 3];
            *(float4*)(op + n4 * 4) = v;
        }
    }
}

// ---------------- chunked selective scan (3 phases) ----------------
__global__ __launch_bounds__(256) void scan_phase1(const float* __restrict__ A_log)
{
    const int tid = threadIdx.x;
    const int s = tid & 15;
    const int G = blockIdx.x * 16 + (tid >> 4);   // (b*NC + c)*DD + d
    const int d = G % DD;
    const int t2 = G / DD;
    const int c = t2 % NC;
    const int b = t2 / NC;

    const float Acoef = -expf(A_log[d * SS + s]);
    const int l0 = c * LC;
    const float* dtp = g_dt    + ((size_t)(b * LL + l0)) * DD + d;
    const float* xcp = g_xconv + ((size_t)(b * LL + l0)) * DD + d;
    const float* bcp = g_bc    + ((size_t)(b * LL + l0)) * 32;

    float h = 0.f, P = 1.f;
    for (int i = 0; i < LC; i++) {
        float dtv = dtp[(size_t)i * DD];
        float xcv = xcp[(size_t)i * DD];
        float Bv  = bcp[i * 32 + s];
        float dA = expf(dtv * Acoef);
        P *= dA;
        h = fmaf(dA, h, dtv * Bv * xcv);
    }
    int idx = (((b * DD + d) * NC) + c) * SS + s;
    g_P[idx] = P;
    g_hend[idx] = h;
}

__global__ __launch_bounds__(256) void scan_phase2()
{
    int t = blockIdx.x * 256 + threadIdx.x;    // < BB*DD*SS
    int s = t & 15;
    int rest = t >> 4;                          // b*DD + d
    int base = rest * NC * SS + s;
    float h = 0.f;
#pragma unroll
    for (int c = 0; c < NC; c++) {
        int idx = base + c * SS;
        g_hin[idx] = h;
        h = fmaf(g_P[idx], h, g_hend[idx]);
    }
}

__global__ __launch_bounds__(256) void scan_phase3(
    const float* __restrict__ A_log, const float* __restrict__ Dp)
{
    const int tid = threadIdx.x;
    const int s = tid & 15;
    const int G = blockIdx.x * 16 + (tid >> 4);
    const int d = G % DD;
    const int t2 = G / DD;
    const int c = t2 % NC;
    const int b = t2 / NC;

    const float Acoef = -expf(A_log[d * SS + s]);
    const float Dv = Dp[d];
    const int l0 = c * LC;

    const float* dtp = g_dt    + ((size_t)(b * LL + l0)) * DD + d;
    const float* xcp = g_xconv + ((size_t)(b * LL + l0)) * DD + d;
    const float* bcp = g_bc    + ((size_t)(b * LL + l0)) * 32;
    const float* zp  = g_xz    + ((size_t)(b * LL + l0)) * TWO_D + DD + d;
    float*       yp  = g_yg    + ((size_t)(b * LL + l0)) * DD + d;

    float h = g_hin[(((b * DD + d) * NC) + c) * SS + s];
    for (int i = 0; i < LC; i++) {
        float dtv = dtp[(size_t)i * DD];
        float xcv = xcp[(size_t)i * DD];
        float Bv  = bcp[i * 32 + s];
        float Cv  = bcp[i * 32 + 16 + s];

        float dA = expf(dtv * Acoef);
        h = fmaf(dA, h, dtv * Bv * xcv);

        float p = h * Cv;
        p += __shfl_xor_sync(0xffffffffu, p, 8);
        p += __shfl_xor_sync(0xffffffffu, p, 4);
        p += __shfl_xor_sync(0xffffffffu, p, 2);
        p += __shfl_xor_sync(0xffffffffu, p, 1);

        if (s == 0) {
            float y = fmaf(Dv, xcv, p);
            float zv = zp[(size_t)i * TWO_D];
            float gz = zv / (1.f + expf(-zv));
            yp[(size_t)i * DD] = y * gz;
        }
    }
}

// ---------------- launch ----------------
extern "C" void kernel_launch(void* const* d_in, const int* in_sizes, int n_in,
                              void* d_out, int out_size)
{
    const float* x      = (const float*)d_in[0];
    const float* w_in   = (const float*)d_in[1];
    const float* conv_w = (const float*)d_in[2];
    const float* conv_b = (const float*)d_in[3];
    const float* w_x    = (const float*)d_in[4];
    const float* w_dt   = (const float*)d_in[5];
    const float* b_dt   = (const float*)d_in[6];
    const float* A_log  = (const float*)d_in[7];
    const float* D_par  = (const float*)d_in[8];
    const float* w_out  = (const float*)d_in[9];
    float* out = (float*)d_out;

    // 0. xz = x @ w_in                       (8192 x 1536, K=768)
    gemm_in_kernel<<<dim3(TWO_D / 128, MM / 128), 256>>>(x, w_in);

    // 1. causal depthwise conv + SiLU
    conv_silu_kernel<<<(MM * DD + 255) / 256, 256>>>(conv_w, conv_b);

    // 2. BC = xconv @ w_x                    (8192 x 32, K=768)
    bc_gemm_kernel<<<MM / 128, 256>>>(w_x);

    // 3. dt = softplus(xconv @ w_dt + b_dt)  (8192 x 768, K=768)  [profile slot]
    gemm_dt_kernel<<<dim3(DD / 128, MM / 128), 256>>>(w_dt, b_dt);

    // 4-6. chunked selective scan + gating   -> yg
    scan_phase1<<<(BB * DD * NC) / 16, 256>>>(A_log);
    scan_phase2<<<(BB * DD * SS) / 256, 256>>>();
    scan_phase3<<<(BB * DD * NC) / 16, 256>>>(A_log, D_par);

    // 7. out = yg @ w_out                    (8192 x 768, K=768)
    gemm_out_kernel<<<dim3(DD / 128, MM / 128), 256>>>(w_out, out);
}